// round 3
// baseline (speedup 1.0000x reference)
#include <cuda_runtime.h>
#include <math.h>

#define NN 50000
#define EE 625000
#define DD 128
#define ROWS_PER_BLOCK 64
#define GEMM_THREADS 256
#define SCAN_T 1024

// Scratch (device globals — no allocation allowed in kernel_launch)
__device__ int   g_deg[2 * NN];                 // raw counts: [0:NN) fwd in-deg by dst, [NN:2NN) bwd (out-deg by src)
__device__ int   g_off[2 * NN];                 // CSR row starts (bwd half offset by EE)
__device__ int   g_cur[2 * NN];                 // fill cursors
__device__ int   g_csr[2 * EE];                 // [0:EE) src lists grouped by dst; [EE:2EE) dst lists grouped by src
__device__ float g_hs_f[(size_t)NN * DD];       // (x@W_fwd) * dinv_f  (row-scaled)
__device__ float g_hs_b[(size_t)NN * DD];

__global__ void k_init_deg() {
    int i = blockIdx.x * blockDim.x + threadIdx.x;
    if (i < 2 * NN) g_deg[i] = 0;
}

__global__ void k_count(const int* __restrict__ ei) {
    int e = blockIdx.x * blockDim.x + threadIdx.x;
    if (e < EE) {
        int s = ei[e];
        int d = ei[EE + e];
        atomicAdd(&g_deg[d], 1);                // fwd conv: degree by dst
        atomicAdd(&g_deg[NN + s], 1);           // bwd conv (edges reversed): by src
    }
}

// Single-block exclusive scan over 2*NN degree counts -> row offsets + cursors.
__global__ void __launch_bounds__(SCAN_T) k_scan() {
    __shared__ int sums[SCAN_T];
    const int total = 2 * NN;
    const int C = (total + SCAN_T - 1) / SCAN_T;     // 98
    int t = threadIdx.x;
    int beg = t * C;
    int end = beg + C; if (end > total) end = total;
    int s = 0;
    for (int i = beg; i < end; i++) s += g_deg[i];
    sums[t] = s;
    __syncthreads();
    for (int off = 1; off < SCAN_T; off <<= 1) {
        int v = (t >= off) ? sums[t - off] : 0;
        __syncthreads();
        sums[t] += v;
        __syncthreads();
    }
    int base = (t == 0) ? 0 : sums[t - 1];           // exclusive prefix
    for (int i = beg; i < end; i++) {
        int d = g_deg[i];
        g_off[i] = base;
        g_cur[i] = base;
        base += d;
    }
}

__global__ void k_fill(const int* __restrict__ ei) {
    int e = blockIdx.x * blockDim.x + threadIdx.x;
    if (e >= EE) return;
    int s = ei[e];
    int d = ei[EE + e];
    int pf = atomicAdd(&g_cur[d], 1);
    g_csr[pf] = s;                                   // fwd: node d receives from s
    int pb = atomicAdd(&g_cur[NN + s], 1);
    g_csr[pb] = d;                                   // bwd: node s receives from d
}

// Fused dual GEMM + dinv row scale. Each block: 64 rows, 256 threads.
__global__ void __launch_bounds__(GEMM_THREADS)
k_gemm(const float* __restrict__ x,
       const float* __restrict__ Wf,
       const float* __restrict__ Wb) {
    extern __shared__ float sm[];
    float* sW = sm;                 // 128*128 floats (64 KB)
    float* sX = sm + DD * DD;       // 64*128 floats (32 KB)
    const int row0 = blockIdx.x * ROWS_PER_BLOCK;
    const int tid  = threadIdx.x;
    const int warp = tid >> 5, lane = tid & 31;

    for (int i = tid; i < ROWS_PER_BLOCK * DD / 4; i += GEMM_THREADS) {
        int r  = i >> 5;
        int gr = row0 + r;
        float4 v = make_float4(0.f, 0.f, 0.f, 0.f);
        if (gr < NN) v = reinterpret_cast<const float4*>(x)[(size_t)gr * 32 + (i & 31)];
        reinterpret_cast<float4*>(sX)[i] = v;
    }

    #pragma unroll
    for (int pass = 0; pass < 2; pass++) {
        const float* W = pass ? Wb : Wf;
        __syncthreads();
        for (int i = tid; i < DD * DD / 4; i += GEMM_THREADS)
            reinterpret_cast<float4*>(sW)[i] = reinterpret_cast<const float4*>(W)[i];
        __syncthreads();

        float4 acc[8];
        #pragma unroll
        for (int r = 0; r < 8; r++) acc[r] = make_float4(0.f, 0.f, 0.f, 0.f);

        const float* xbase = sX + (warp * 8) * DD;
        #pragma unroll 4
        for (int k4 = 0; k4 < 32; k4++) {
            float4 xv[8];
            #pragma unroll
            for (int r = 0; r < 8; r++)
                xv[r] = reinterpret_cast<const float4*>(xbase + (size_t)r * DD)[k4];
            #pragma unroll
            for (int kk = 0; kk < 4; kk++) {
                float4 w = reinterpret_cast<const float4*>(sW)[(k4 * 4 + kk) * 32 + lane];
                #pragma unroll
                for (int r = 0; r < 8; r++) {
                    float xs = (kk == 0) ? xv[r].x : (kk == 1) ? xv[r].y
                             : (kk == 2) ? xv[r].z : xv[r].w;
                    acc[r].x += xs * w.x;
                    acc[r].y += xs * w.y;
                    acc[r].z += xs * w.z;
                    acc[r].w += xs * w.w;
                }
            }
        }

        float* hs = pass ? g_hs_b : g_hs_f;
        const int degoff = pass ? NN : 0;
        #pragma unroll
        for (int r = 0; r < 8; r++) {
            int gr = row0 + warp * 8 + r;
            if (gr < NN) {
                float dinv = rsqrtf((float)(g_deg[degoff + gr] + 1));   // +1 self-loop
                float4 o = acc[r];
                o.x *= dinv; o.y *= dinv; o.z *= dinv; o.w *= dinv;
                reinterpret_cast<float4*>(hs)[(size_t)gr * 32 + lane] = o;
            }
        }
    }
}

// Pull aggregation: one warp per node, both convs, fused finalize.
// Lane owns 4 consecutive cols (float4 per row).
__global__ void __launch_bounds__(256)
k_agg(const float* __restrict__ bf,
      const float* __restrict__ bb,
      float* __restrict__ out) {
    int w = (blockIdx.x * blockDim.x + threadIdx.x) >> 5;
    int lane = threadIdx.x & 31;
    if (w >= NN) return;
    const int v = w;

    const float4* hsf = reinterpret_cast<const float4*>(g_hs_f);
    const float4* hsb = reinterpret_cast<const float4*>(g_hs_b);

    // fwd: self loop + incoming neighbors
    float4 af = hsf[(size_t)v * 32 + lane];
    {
        int beg = g_off[v];
        int end = beg + g_deg[v];
        int i = beg;
        for (; i + 4 <= end; i += 4) {
            int i0 = g_csr[i], i1 = g_csr[i + 1], i2 = g_csr[i + 2], i3 = g_csr[i + 3];
            float4 v0 = hsf[(size_t)i0 * 32 + lane];
            float4 v1 = hsf[(size_t)i1 * 32 + lane];
            float4 v2 = hsf[(size_t)i2 * 32 + lane];
            float4 v3 = hsf[(size_t)i3 * 32 + lane];
            af.x += (v0.x + v1.x) + (v2.x + v3.x);
            af.y += (v0.y + v1.y) + (v2.y + v3.y);
            af.z += (v0.z + v1.z) + (v2.z + v3.z);
            af.w += (v0.w + v1.w) + (v2.w + v3.w);
        }
        for (; i < end; i++) {
            int idx = g_csr[i];
            float4 t = hsf[(size_t)idx * 32 + lane];
            af.x += t.x; af.y += t.y; af.z += t.z; af.w += t.w;
        }
    }

    // bwd
    float4 ab = hsb[(size_t)v * 32 + lane];
    {
        int beg = g_off[NN + v];
        int end = beg + g_deg[NN + v];
        int i = beg;
        for (; i + 4 <= end; i += 4) {
            int i0 = g_csr[i], i1 = g_csr[i + 1], i2 = g_csr[i + 2], i3 = g_csr[i + 3];
            float4 v0 = hsb[(size_t)i0 * 32 + lane];
            float4 v1 = hsb[(size_t)i1 * 32 + lane];
            float4 v2 = hsb[(size_t)i2 * 32 + lane];
            float4 v3 = hsb[(size_t)i3 * 32 + lane];
            ab.x += (v0.x + v1.x) + (v2.x + v3.x);
            ab.y += (v0.y + v1.y) + (v2.y + v3.y);
            ab.z += (v0.z + v1.z) + (v2.z + v3.z);
            ab.w += (v0.w + v1.w) + (v2.w + v3.w);
        }
        for (; i < end; i++) {
            int idx = g_csr[i];
            float4 t = hsb[(size_t)idx * 32 + lane];
            ab.x += t.x; ab.y += t.y; ab.z += t.z; ab.w += t.w;
        }
    }

    float df = rsqrtf((float)(g_deg[v] + 1));
    float db = rsqrtf((float)(g_deg[NN + v] + 1));
    float4 vf = reinterpret_cast<const float4*>(bf)[lane];
    float4 vb = reinterpret_cast<const float4*>(bb)[lane];
    float4 o;
    o.x = fmaxf(af.x * df + ab.x * db + vf.x + vb.x, 0.f);
    o.y = fmaxf(af.y * df + ab.y * db + vf.y + vb.y, 0.f);
    o.z = fmaxf(af.z * df + ab.z * db + vf.z + vb.z, 0.f);
    o.w = fmaxf(af.w * df + ab.w * db + vf.w + vb.w, 0.f);
    reinterpret_cast<float4*>(out)[(size_t)v * 32 + lane] = o;
}

extern "C" void kernel_launch(void* const* d_in, const int* in_sizes, int n_in,
                              void* d_out, int out_size) {
    const float* x  = (const float*)d_in[0];
    const int*   ei = (const int*)  d_in[1];
    const float* Wf = (const float*)d_in[2];
    const float* bf = (const float*)d_in[3];
    const float* Wb = (const float*)d_in[4];
    const float* bb = (const float*)d_in[5];
    float*       out = (float*)d_out;

    const int smem = (DD * DD + ROWS_PER_BLOCK * DD) * (int)sizeof(float); // 96 KB
    cudaFuncSetAttribute(k_gemm, cudaFuncAttributeMaxDynamicSharedMemorySize, smem);

    k_init_deg<<<(2 * NN + 255) / 256, 256>>>();
    k_count<<<(EE + 255) / 256, 256>>>(ei);
    k_scan<<<1, SCAN_T>>>();
    k_fill<<<(EE + 255) / 256, 256>>>(ei);
    k_gemm<<<(NN + ROWS_PER_BLOCK - 1) / ROWS_PER_BLOCK, GEMM_THREADS, smem>>>(x, Wf, Wb);
    k_agg<<<(NN * 32 + 255) / 256, 256>>>(bf, bb, out);
}